// round 1
// baseline (speedup 1.0000x reference)
#include <cuda_runtime.h>
#include <cuda_bf16.h>
#include <cstdint>

// Problem constants (fixed shapes for this problem instance)
#define NMAX 100000
#define EMAX 1600000
#define DIN  128
#define DHID 128   // hidden width; also width of fused [W_mu|W_ls] GEMM output
#define DLAT 64

// ---------------- scratch (static device globals; no allocation allowed) ----
__device__ float g_bufA[(size_t)NMAX * DHID];  // h0, later h2 (fused mu|ls pre-agg)
__device__ float g_bufB[(size_t)NMAX * DHID];  // agg1, later agg2
__device__ float g_bufH[(size_t)NMAX * DHID];  // h (post-relu hidden)
__device__ float g_dinv[NMAX];                 // deg -> dinv in place
__device__ int   g_src[EMAX];
__device__ int   g_dst[EMAX];
__device__ int   g_idx64;                      // 1 if edge_index is int64

// ---------------- edge dtype detection + conversion -------------------------
__global__ void k_detect(const long long* ei, int N) {
    if (threadIdx.x == 0 && blockIdx.x == 0) {
        int ok64 = 1;
        #pragma unroll
        for (int k = 0; k < 8; k++) {
            long long v = ei[k];
            if (v < 0 || v >= (long long)N) ok64 = 0;
        }
        g_idx64 = ok64;
    }
}

__global__ void k_convert(const void* ei, int E) {
    int e = blockIdx.x * blockDim.x + threadIdx.x;
    if (e >= E) return;
    if (g_idx64) {
        const long long* p = (const long long*)ei;
        g_src[e] = (int)p[e];
        g_dst[e] = (int)p[(size_t)E + e];
    } else {
        const int* p = (const int*)ei;
        g_src[e] = p[e];
        g_dst[e] = p[E + e];
    }
}

// ---------------- degree / normalization ------------------------------------
__global__ void k_deg_init(float* deg, int N) {
    int i = blockIdx.x * blockDim.x + threadIdx.x;
    if (i < N) deg[i] = 1.0f;   // self-loop contributes 1
}

__global__ void k_deg_count(float* deg, int E) {
    int e = blockIdx.x * blockDim.x + threadIdx.x;
    if (e < E) atomicAdd(&deg[g_dst[e]], 1.0f);
}

__global__ void k_dinv(float* deg, int N) {
    int i = blockIdx.x * blockDim.x + threadIdx.x;
    if (i < N) deg[i] = rsqrtf(deg[i]);   // deg >= 1 always
}

// ---------------- fp32 GEMM: C[N,128] = A[N,128] @ [B0 | B1] ----------------
// Block tile 64 rows x 128 cols, 256 threads, each thread 8 rows x 4 cols.
// B is given as two half-matrices (cols 0..63 from B0, 64..127 from B1) so the
// same kernel serves W1 (ldb=128, B1 = W1+64) and the fused [W_mu|W_ls].
__global__ __launch_bounds__(256) void k_gemm(
    const float* __restrict__ A,
    const float* __restrict__ B0, const float* __restrict__ B1,
    int ldb0, int ldb1,
    float* __restrict__ C, int N)
{
    __shared__ float As[8][64];
    __shared__ float Bs[8][128];

    int t  = threadIdx.x;
    int tx = t & 31;          // col group: cols [4*tx, 4*tx+3]
    int ty = t >> 5;          // row group: rows [8*ty, 8*ty+7] in tile
    int row0 = blockIdx.x * 64;

    float4 acc[8];
    #pragma unroll
    for (int i = 0; i < 8; i++) acc[i] = make_float4(0.f, 0.f, 0.f, 0.f);

    int lr = t >> 2;          // A-load row (0..63)
    int lk = (t & 3) * 2;     // A-load k offset (0,2,4,6)
    int bj = t & 127;         // B-load col
    int bkb = t >> 7;         // 0 or 1

    for (int k0 = 0; k0 < DIN; k0 += 8) {
        int grow = row0 + lr;
        float a0 = 0.f, a1 = 0.f;
        if (grow < N) {
            a0 = A[(size_t)grow * DIN + k0 + lk];
            a1 = A[(size_t)grow * DIN + k0 + lk + 1];
        }
        As[lk][lr]     = a0;
        As[lk + 1][lr] = a1;

        #pragma unroll
        for (int u = 0; u < 4; u++) {
            int kk = bkb + u * 2;
            int kg = k0 + kk;
            float bv = (bj < 64) ? B0[kg * ldb0 + bj]
                                 : B1[kg * ldb1 + (bj - 64)];
            Bs[kk][bj] = bv;
        }
        __syncthreads();

        #pragma unroll
        for (int kk = 0; kk < 8; kk++) {
            float4 bv = *(const float4*)&Bs[kk][tx * 4];
            #pragma unroll
            for (int i = 0; i < 8; i++) {
                float av = As[kk][ty * 8 + i];
                acc[i].x += av * bv.x;
                acc[i].y += av * bv.y;
                acc[i].z += av * bv.z;
                acc[i].w += av * bv.w;
            }
        }
        __syncthreads();
    }

    #pragma unroll
    for (int i = 0; i < 8; i++) {
        int grow = row0 + ty * 8 + i;
        if (grow < N)
            *(float4*)&C[(size_t)grow * DHID + tx * 4] = acc[i];
    }
}

// ---------------- edge scatter: agg[dst] += norm * feat[src] ----------------
// One warp per edge; 32 lanes x float4 = 128 floats. Vector red.global v4.
__global__ __launch_bounds__(256) void k_scatter(
    const float* __restrict__ feat,
    const float* __restrict__ dinv,
    float* __restrict__ agg, int E)
{
    int w    = (blockIdx.x * blockDim.x + threadIdx.x) >> 5;
    int lane = threadIdx.x & 31;
    if (w >= E) return;
    int s = g_src[w];
    int d = g_dst[w];
    float nw = __ldg(&dinv[s]) * __ldg(&dinv[d]);
    float4 v = *(const float4*)&feat[(size_t)s * DHID + lane * 4];
    v.x *= nw; v.y *= nw; v.z *= nw; v.w *= nw;
    float* p = &agg[(size_t)d * DHID + lane * 4];
    asm volatile("red.global.add.v4.f32 [%0], {%1, %2, %3, %4};"
                 :: "l"(p), "f"(v.x), "f"(v.y), "f"(v.z), "f"(v.w)
                 : "memory");
}

// ---------------- epilogue 1: h = relu(agg + dinv^2 * h0 + b1) --------------
__global__ void k_epi1(const float* __restrict__ agg, const float* __restrict__ h0,
                       const float* __restrict__ dinv, const float* __restrict__ b1,
                       float* __restrict__ h, int N)
{
    int idx = blockIdx.x * blockDim.x + threadIdx.x;
    if (idx >= N * 32) return;
    int i = idx >> 5, j4 = idx & 31;
    float di = dinv[i];
    float w = di * di;
    float4 a = *(const float4*)&agg[(size_t)i * DHID + j4 * 4];
    float4 s = *(const float4*)&h0[(size_t)i * DHID + j4 * 4];
    float4 b = *(const float4*)&b1[j4 * 4];
    float4 r;
    r.x = fmaxf(fmaf(w, s.x, a.x) + b.x, 0.f);
    r.y = fmaxf(fmaf(w, s.y, a.y) + b.y, 0.f);
    r.z = fmaxf(fmaf(w, s.z, a.z) + b.z, 0.f);
    r.w = fmaxf(fmaf(w, s.w, a.w) + b.w, 0.f);
    *(float4*)&h[(size_t)i * DHID + j4 * 4] = r;
}

// ---------------- epilogue 2: split into mu / logstd + biases ---------------
__global__ void k_epi2(const float* __restrict__ agg, const float* __restrict__ h2,
                       const float* __restrict__ dinv,
                       const float* __restrict__ bmu, const float* __restrict__ bls,
                       float* __restrict__ out, int N)
{
    int idx = blockIdx.x * blockDim.x + threadIdx.x;
    if (idx >= N * 32) return;
    int i = idx >> 5, j4 = idx & 31;
    int j = j4 * 4;
    float di = dinv[i];
    float w = di * di;
    float4 a = *(const float4*)&agg[(size_t)i * DHID + j];
    float4 s = *(const float4*)&h2[(size_t)i * DHID + j];
    float4 r;
    r.x = fmaf(w, s.x, a.x);
    r.y = fmaf(w, s.y, a.y);
    r.z = fmaf(w, s.z, a.z);
    r.w = fmaf(w, s.w, a.w);
    if (j < DLAT) {
        float4 b = *(const float4*)&bmu[j];
        r.x += b.x; r.y += b.y; r.z += b.z; r.w += b.w;
        *(float4*)&out[(size_t)i * DLAT + j] = r;
    } else {
        float4 b = *(const float4*)&bls[j - DLAT];
        r.x += b.x; r.y += b.y; r.z += b.z; r.w += b.w;
        *(float4*)&out[(size_t)N * DLAT + (size_t)i * DLAT + (j - DLAT)] = r;
    }
}

// ---------------- launch -----------------------------------------------------
extern "C" void kernel_launch(void* const* d_in, const int* in_sizes, int n_in,
                              void* d_out, int out_size)
{
    const float*     x   = (const float*)d_in[0];
    const void*      ei  = d_in[1];
    const float*     W1  = (const float*)d_in[2];
    const float*     b1  = (const float*)d_in[3];
    const float*     Wmu = (const float*)d_in[4];
    const float*     bmu = (const float*)d_in[5];
    const float*     Wls = (const float*)d_in[6];
    const float*     bls = (const float*)d_in[7];
    float*           out = (float*)d_out;

    int DH = in_sizes[3];                 // 128
    int N  = in_sizes[0] / DIN;           // 100000
    int E  = in_sizes[1] / 2;             // 1600000
    (void)DH; (void)n_in; (void)out_size;

    float *bufA, *bufB, *bufH, *dinv;
    cudaGetSymbolAddress((void**)&bufA, g_bufA);
    cudaGetSymbolAddress((void**)&bufB, g_bufB);
    cudaGetSymbolAddress((void**)&bufH, g_bufH);
    cudaGetSymbolAddress((void**)&dinv, g_dinv);

    size_t featBytes = (size_t)N * DHID * sizeof(float);

    // Edge dtype detect + convert to int32 src/dst
    k_detect<<<1, 32>>>((const long long*)ei, N);
    k_convert<<<(E + 255) / 256, 256>>>(ei, E);

    // Zero accumulator for layer 1
    cudaMemsetAsync(bufB, 0, featBytes, 0);

    // Degree / dinv
    k_deg_init<<<(N + 255) / 256, 256>>>(dinv, N);
    k_deg_count<<<(E + 255) / 256, 256>>>(dinv, E);
    k_dinv<<<(N + 255) / 256, 256>>>(dinv, N);

    // Layer 1: h0 = x @ W1; scatter; h = relu(agg + dinv^2*h0 + b1)
    k_gemm<<<(N + 63) / 64, 256>>>(x, W1, W1 + 64, DHID, DHID, bufA, N);
    {
        long long threads = (long long)E * 32;
        k_scatter<<<(unsigned)((threads + 255) / 256), 256>>>(bufA, dinv, bufB, E);
    }
    k_epi1<<<(N * 32 + 255) / 256, 256>>>(bufB, bufA, dinv, b1, bufH, N);

    // Layer 2 (mu & logstd fused): h2 = h @ [W_mu | W_ls]; scatter; epilogue
    cudaMemsetAsync(bufB, 0, featBytes, 0);
    k_gemm<<<(N + 63) / 64, 256>>>(bufH, Wmu, Wls, DLAT, DLAT, bufA, N);
    {
        long long threads = (long long)E * 32;
        k_scatter<<<(unsigned)((threads + 255) / 256), 256>>>(bufA, dinv, bufB, E);
    }
    k_epi2<<<(N * 32 + 255) / 256, 256>>>(bufB, bufA, dinv, bmu, bls, out, N);
}

// round 3
// speedup vs baseline: 2.0426x; 2.0426x over previous
#include <cuda_runtime.h>
#include <cuda_bf16.h>
#include <cstdint>

#define NMAX 100000
#define EMAX 1600000
#define DIN  128
#define DHID 128
#define DLAT 64

// ---------------- scratch ----------------------------------------------------
__device__ float g_bufA[(size_t)NMAX * DHID];  // feat' (dinv-scaled GEMM out)
__device__ float g_bufH[(size_t)NMAX * DHID];  // hidden h
__device__ float g_dinv[NMAX];
__device__ int   g_src[EMAX];
__device__ int   g_dst[EMAX];
__device__ int   g_adj[EMAX];                  // CSR: src per slot
__device__ int   g_rowptr[NMAX + 1];
__device__ int   g_cnt[NMAX];                  // histogram, then cursor
__device__ int   g_part[512];
__device__ int   g_idx64;

// ---------------- f32x2 helpers ----------------------------------------------
__device__ __forceinline__ unsigned long long pk2(float lo, float hi) {
    unsigned long long r;
    asm("mov.b64 %0, {%1,%2};" : "=l"(r) : "f"(lo), "f"(hi));
    return r;
}
__device__ __forceinline__ void upk2(unsigned long long v, float& lo, float& hi) {
    asm("mov.b64 {%0,%1}, %2;" : "=f"(lo), "=f"(hi) : "l"(v));
}
__device__ __forceinline__ void ffma2(unsigned long long& acc,
                                      unsigned long long a, unsigned long long b) {
    asm("fma.rn.f32x2 %0, %1, %2, %3;" : "=l"(acc) : "l"(a), "l"(b), "l"(acc));
}

// ---------------- edge dtype detection + conversion (+histogram) -------------
__global__ void k_detect(const long long* ei, int N) {
    if (threadIdx.x == 0 && blockIdx.x == 0) {
        int ok64 = 1;
        #pragma unroll
        for (int k = 0; k < 8; k++) {
            long long v = ei[k];
            if (v < 0 || v >= (long long)N) ok64 = 0;
        }
        g_idx64 = ok64;
    }
}

__global__ void k_convert(const void* ei, int E, int* cnt) {
    int e = blockIdx.x * blockDim.x + threadIdx.x;
    if (e >= E) return;
    int s, d;
    if (g_idx64) {
        const long long* p = (const long long*)ei;
        s = (int)p[e];
        d = (int)p[(size_t)E + e];
    } else {
        const int* p = (const int*)ei;
        s = p[e];
        d = p[E + e];
    }
    g_src[e] = s;
    g_dst[e] = d;
    atomicAdd(&cnt[d], 1);
}

// ---------------- two-level exclusive scan over cnt -> rowptr ----------------
__global__ void k_scan1(const int* cnt, int* rowptr, int* part, int N) {
    __shared__ int sh[256];
    int i = blockIdx.x * 256 + threadIdx.x;
    int v = (i < N) ? cnt[i] : 0;
    sh[threadIdx.x] = v;
    __syncthreads();
    for (int off = 1; off < 256; off <<= 1) {
        int t = (threadIdx.x >= (unsigned)off) ? sh[threadIdx.x - off] : 0;
        __syncthreads();
        sh[threadIdx.x] += t;
        __syncthreads();
    }
    if (i < N) rowptr[i] = sh[threadIdx.x] - v;      // exclusive
    if (threadIdx.x == 255) part[blockIdx.x] = sh[255];
}

__global__ void k_scan2(int* part, int B) {
    __shared__ int sh[512];
    int v = (threadIdx.x < (unsigned)B) ? part[threadIdx.x] : 0;
    sh[threadIdx.x] = v;
    __syncthreads();
    for (int off = 1; off < 512; off <<= 1) {
        int t = (threadIdx.x >= (unsigned)off) ? sh[threadIdx.x - off] : 0;
        __syncthreads();
        sh[threadIdx.x] += t;
        __syncthreads();
    }
    if (threadIdx.x < (unsigned)B) part[threadIdx.x] = sh[threadIdx.x] - v;  // exclusive
}

__global__ void k_scan3(int* rowptr, const int* part, int* cnt, float* dinv,
                        int N, int E) {
    int i = blockIdx.x * 256 + threadIdx.x;
    if (i < N) {
        rowptr[i] += part[blockIdx.x];
        dinv[i] = rsqrtf((float)(cnt[i] + 1));   // +1 self-loop
        cnt[i] = 0;                               // reset as fill cursor
    }
    if (i == 0) rowptr[N] = E;
}

__global__ void k_fill(int E, const int* rowptr, int* cur) {
    int e = blockIdx.x * blockDim.x + threadIdx.x;
    if (e >= E) return;
    int d = g_dst[e];
    int pos = rowptr[d] + atomicAdd(&cur[d], 1);
    g_adj[pos] = g_src[e];
}

// ---------------- fp32 GEMM (f32x2 packed FMA), output scaled by dinv --------
// C[row, :] = dinv[row] * (A[row, :] @ [B0 | B1])
__global__ __launch_bounds__(256) void k_gemm(
    const float* __restrict__ A,
    const float* __restrict__ B0, const float* __restrict__ B1,
    int ldb0, int ldb1,
    const float* __restrict__ dinv,
    float* __restrict__ C, int N)
{
    __shared__ float As[8][64];
    __shared__ float Bs[8][128];

    int t  = threadIdx.x;
    int tx = t & 31;
    int ty = t >> 5;
    int row0 = blockIdx.x * 64;

    unsigned long long acc[8][2];
    #pragma unroll
    for (int i = 0; i < 8; i++) { acc[i][0] = 0ull; acc[i][1] = 0ull; }

    int lr = t >> 2;
    int lk = (t & 3) * 2;
    int bj = t & 127;
    int bkb = t >> 7;
    bool rowOK = (row0 + lr) < N;

    for (int k0 = 0; k0 < DIN; k0 += 8) {
        float a0 = 0.f, a1 = 0.f;
        if (rowOK) {
            const float* ap = &A[(size_t)(row0 + lr) * DIN + k0 + lk];
            a0 = ap[0]; a1 = ap[1];
        }
        As[lk][lr]     = a0;
        As[lk + 1][lr] = a1;

        #pragma unroll
        for (int u = 0; u < 4; u++) {
            int kk = bkb + u * 2;
            int kg = k0 + kk;
            float bv = (bj < 64) ? B0[kg * ldb0 + bj]
                                 : B1[kg * ldb1 + (bj - 64)];
            Bs[kk][bj] = bv;
        }
        __syncthreads();

        #pragma unroll
        for (int kk = 0; kk < 8; kk++) {
            float4 bv = *(const float4*)&Bs[kk][tx * 4];
            unsigned long long b01 = pk2(bv.x, bv.y);
            unsigned long long b23 = pk2(bv.z, bv.w);
            #pragma unroll
            for (int i = 0; i < 8; i++) {
                float av = As[kk][ty * 8 + i];
                unsigned long long ad = pk2(av, av);
                ffma2(acc[i][0], ad, b01);
                ffma2(acc[i][1], ad, b23);
            }
        }
        __syncthreads();
    }

    #pragma unroll
    for (int i = 0; i < 8; i++) {
        int grow = row0 + ty * 8 + i;
        if (grow < N) {
            float di = dinv[grow];
            float4 r;
            upk2(acc[i][0], r.x, r.y);
            upk2(acc[i][1], r.z, r.w);
            r.x *= di; r.y *= di; r.z *= di; r.w *= di;
            *(float4*)&C[(size_t)grow * DHID + tx * 4] = r;
        }
    }
}

// ---------------- gather layer 1: h = relu(dinv[d]*(self + sum) + b1) --------
__global__ __launch_bounds__(256) void k_gather1(
    const float* __restrict__ feat, const int* __restrict__ rowptr,
    const int* __restrict__ adj, const float* __restrict__ dinv,
    const float* __restrict__ b1, float* __restrict__ outh, int N)
{
    int node = (blockIdx.x * blockDim.x + threadIdx.x) >> 5;
    int lane = threadIdx.x & 31;
    if (node >= N) return;
    int beg = rowptr[node], end = rowptr[node + 1];

    float4 acc = *(const float4*)&feat[(size_t)node * DHID + lane * 4];  // self
    int p = beg;
    for (; p + 4 <= end; p += 4) {
        int s0 = __ldg(&adj[p]);
        int s1 = __ldg(&adj[p + 1]);
        int s2 = __ldg(&adj[p + 2]);
        int s3 = __ldg(&adj[p + 3]);
        float4 v0 = *(const float4*)&feat[(size_t)s0 * DHID + lane * 4];
        float4 v1 = *(const float4*)&feat[(size_t)s1 * DHID + lane * 4];
        float4 v2 = *(const float4*)&feat[(size_t)s2 * DHID + lane * 4];
        float4 v3 = *(const float4*)&feat[(size_t)s3 * DHID + lane * 4];
        acc.x += v0.x + v1.x + v2.x + v3.x;
        acc.y += v0.y + v1.y + v2.y + v3.y;
        acc.z += v0.z + v1.z + v2.z + v3.z;
        acc.w += v0.w + v1.w + v2.w + v3.w;
    }
    for (; p < end; p++) {
        int s = __ldg(&adj[p]);
        float4 v = *(const float4*)&feat[(size_t)s * DHID + lane * 4];
        acc.x += v.x; acc.y += v.y; acc.z += v.z; acc.w += v.w;
    }

    float di = dinv[node];
    float4 b = *(const float4*)&b1[lane * 4];
    float4 r;
    r.x = fmaxf(fmaf(di, acc.x, b.x), 0.f);
    r.y = fmaxf(fmaf(di, acc.y, b.y), 0.f);
    r.z = fmaxf(fmaf(di, acc.z, b.z), 0.f);
    r.w = fmaxf(fmaf(di, acc.w, b.w), 0.f);
    *(float4*)&outh[(size_t)node * DHID + lane * 4] = r;
}

// ---------------- gather layer 2: mu / logstd split --------------------------
__global__ __launch_bounds__(256) void k_gather2(
    const float* __restrict__ feat, const int* __restrict__ rowptr,
    const int* __restrict__ adj, const float* __restrict__ dinv,
    const float* __restrict__ bmu, const float* __restrict__ bls,
    float* __restrict__ out, int N)
{
    int node = (blockIdx.x * blockDim.x + threadIdx.x) >> 5;
    int lane = threadIdx.x & 31;
    if (node >= N) return;
    int beg = rowptr[node], end = rowptr[node + 1];

    float4 acc = *(const float4*)&feat[(size_t)node * DHID + lane * 4];  // self
    int p = beg;
    for (; p + 4 <= end; p += 4) {
        int s0 = __ldg(&adj[p]);
        int s1 = __ldg(&adj[p + 1]);
        int s2 = __ldg(&adj[p + 2]);
        int s3 = __ldg(&adj[p + 3]);
        float4 v0 = *(const float4*)&feat[(size_t)s0 * DHID + lane * 4];
        float4 v1 = *(const float4*)&feat[(size_t)s1 * DHID + lane * 4];
        float4 v2 = *(const float4*)&feat[(size_t)s2 * DHID + lane * 4];
        float4 v3 = *(const float4*)&feat[(size_t)s3 * DHID + lane * 4];
        acc.x += v0.x + v1.x + v2.x + v3.x;
        acc.y += v0.y + v1.y + v2.y + v3.y;
        acc.z += v0.z + v1.z + v2.z + v3.z;
        acc.w += v0.w + v1.w + v2.w + v3.w;
    }
    for (; p < end; p++) {
        int s = __ldg(&adj[p]);
        float4 v = *(const float4*)&feat[(size_t)s * DHID + lane * 4];
        acc.x += v.x; acc.y += v.y; acc.z += v.z; acc.w += v.w;
    }

    float di = dinv[node];
    int j = lane * 4;
    float4 r;
    if (j < DLAT) {
        float4 b = *(const float4*)&bmu[j];
        r.x = fmaf(di, acc.x, b.x);
        r.y = fmaf(di, acc.y, b.y);
        r.z = fmaf(di, acc.z, b.z);
        r.w = fmaf(di, acc.w, b.w);
        *(float4*)&out[(size_t)node * DLAT + j] = r;
    } else {
        float4 b = *(const float4*)&bls[j - DLAT];
        r.x = fmaf(di, acc.x, b.x);
        r.y = fmaf(di, acc.y, b.y);
        r.z = fmaf(di, acc.z, b.z);
        r.w = fmaf(di, acc.w, b.w);
        *(float4*)&out[(size_t)N * DLAT + (size_t)node * DLAT + (j - DLAT)] = r;
    }
}

// ---------------- launch ------------------------------------------------------
extern "C" void kernel_launch(void* const* d_in, const int* in_sizes, int n_in,
                              void* d_out, int out_size)
{
    const float* x   = (const float*)d_in[0];
    const void*  ei  = d_in[1];
    const float* W1  = (const float*)d_in[2];
    const float* b1  = (const float*)d_in[3];
    const float* Wmu = (const float*)d_in[4];
    const float* bmu = (const float*)d_in[5];
    const float* Wls = (const float*)d_in[6];
    const float* bls = (const float*)d_in[7];
    float*       out = (float*)d_out;

    int N = in_sizes[0] / DIN;     // 100000
    int E = in_sizes[1] / 2;       // 1600000
    (void)n_in; (void)out_size;

    float *bufA, *bufH, *dinv;
    int *cnt, *rowptr, *part, *adj;
    cudaGetSymbolAddress((void**)&bufA, g_bufA);
    cudaGetSymbolAddress((void**)&bufH, g_bufH);
    cudaGetSymbolAddress((void**)&dinv, g_dinv);
    cudaGetSymbolAddress((void**)&cnt, g_cnt);
    cudaGetSymbolAddress((void**)&rowptr, g_rowptr);
    cudaGetSymbolAddress((void**)&part, g_part);
    cudaGetSymbolAddress((void**)&adj, g_adj);     // <-- was passed as raw symbol (bug)

    int B = (N + 255) / 256;       // scan blocks (391)

    // ---- edge preprocessing: detect, convert+histogram, scan, fill ----
    k_detect<<<1, 32>>>((const long long*)ei, N);
    cudaMemsetAsync(cnt, 0, (size_t)N * sizeof(int), 0);
    k_convert<<<(E + 255) / 256, 256>>>(ei, E, cnt);
    k_scan1<<<B, 256>>>(cnt, rowptr, part, N);
    k_scan2<<<1, 512>>>(part, B);
    k_scan3<<<B, 256>>>(rowptr, part, cnt, dinv, N, E);
    k_fill<<<(E + 255) / 256, 256>>>(E, rowptr, cnt);

    // ---- layer 1 ----
    k_gemm<<<(N + 63) / 64, 256>>>(x, W1, W1 + 64, DHID, DHID, dinv, bufA, N);
    k_gather1<<<(N * 32 + 255) / 256, 256>>>(bufA, rowptr, adj, dinv, b1, bufH, N);

    // ---- layer 2 (mu | logstd fused) ----
    k_gemm<<<(N + 63) / 64, 256>>>(bufH, Wmu, Wls, DLAT, DLAT, dinv, bufA, N);
    k_gather2<<<(N * 32 + 255) / 256, 256>>>(bufA, rowptr, adj, dinv, bmu, bls, out, N);
}

// round 4
// speedup vs baseline: 2.2342x; 1.0938x over previous
#include <cuda_runtime.h>
#include <cuda_fp16.h>
#include <cstdint>

#define NMAX 100000
#define EMAX 1600000
#define DIN  128
#define DHID 128
#define DLAT 64

// ---------------- scratch ----------------------------------------------------
struct alignas(8) h2x2 { __half2 a, b; };

__device__ __half2 g_feat[(size_t)NMAX * 64];  // fp16 feat' (dinv-scaled GEMM out)
__device__ float   g_bufH[(size_t)NMAX * DHID]; // hidden h (fp32)
__device__ float   g_dinv[NMAX];
__device__ int     g_src[EMAX];
__device__ int     g_dst[EMAX];
__device__ int     g_adj[EMAX];                 // CSR: src per slot
__device__ int     g_rowptr[NMAX + 1];
__device__ int     g_cnt[NMAX];                 // histogram, then cursor
__device__ int     g_part[512];
__device__ int     g_idx64;

// ---------------- f32x2 helpers ----------------------------------------------
__device__ __forceinline__ unsigned long long pk2(float lo, float hi) {
    unsigned long long r;
    asm("mov.b64 %0, {%1,%2};" : "=l"(r) : "f"(lo), "f"(hi));
    return r;
}
__device__ __forceinline__ void upk2(unsigned long long v, float& lo, float& hi) {
    asm("mov.b64 {%0,%1}, %2;" : "=f"(lo), "=f"(hi) : "l"(v));
}
__device__ __forceinline__ void ffma2(unsigned long long& acc,
                                      unsigned long long a, unsigned long long b) {
    asm("fma.rn.f32x2 %0, %1, %2, %3;" : "=l"(acc) : "l"(a), "l"(b), "l"(acc));
}

// ---------------- edge dtype detection + conversion (+histogram) -------------
__global__ void k_detect(const long long* ei, int N) {
    if (threadIdx.x == 0 && blockIdx.x == 0) {
        int ok64 = 1;
        #pragma unroll
        for (int k = 0; k < 8; k++) {
            long long v = ei[k];
            if (v < 0 || v >= (long long)N) ok64 = 0;
        }
        g_idx64 = ok64;
    }
}

__global__ void k_convert(const void* ei, int E, int* cnt) {
    int e = blockIdx.x * blockDim.x + threadIdx.x;
    if (e >= E) return;
    int s, d;
    if (g_idx64) {
        const long long* p = (const long long*)ei;
        s = (int)p[e];
        d = (int)p[(size_t)E + e];
    } else {
        const int* p = (const int*)ei;
        s = p[e];
        d = p[E + e];
    }
    g_src[e] = s;
    g_dst[e] = d;
    atomicAdd(&cnt[d], 1);
}

// ---------------- two-level exclusive scan over cnt -> rowptr ----------------
__global__ void k_scan1(const int* cnt, int* rowptr, int* part, int N) {
    __shared__ int sh[256];
    int i = blockIdx.x * 256 + threadIdx.x;
    int v = (i < N) ? cnt[i] : 0;
    sh[threadIdx.x] = v;
    __syncthreads();
    for (int off = 1; off < 256; off <<= 1) {
        int t = (threadIdx.x >= (unsigned)off) ? sh[threadIdx.x - off] : 0;
        __syncthreads();
        sh[threadIdx.x] += t;
        __syncthreads();
    }
    if (i < N) rowptr[i] = sh[threadIdx.x] - v;      // exclusive
    if (threadIdx.x == 255) part[blockIdx.x] = sh[255];
}

__global__ void k_scan2(int* part, int B) {
    __shared__ int sh[512];
    int v = (threadIdx.x < (unsigned)B) ? part[threadIdx.x] : 0;
    sh[threadIdx.x] = v;
    __syncthreads();
    for (int off = 1; off < 512; off <<= 1) {
        int t = (threadIdx.x >= (unsigned)off) ? sh[threadIdx.x - off] : 0;
        __syncthreads();
        sh[threadIdx.x] += t;
        __syncthreads();
    }
    if (threadIdx.x < (unsigned)B) part[threadIdx.x] = sh[threadIdx.x] - v;  // exclusive
}

__global__ void k_scan3(int* rowptr, const int* part, int* cnt, float* dinv,
                        int N, int E) {
    int i = blockIdx.x * 256 + threadIdx.x;
    if (i < N) {
        rowptr[i] += part[blockIdx.x];
        dinv[i] = rsqrtf((float)(cnt[i] + 1));   // +1 self-loop
        cnt[i] = 0;                               // reset as fill cursor
    }
    if (i == 0) rowptr[N] = E;
}

__global__ void k_fill(int E, const int* rowptr, int* cur, int* adj) {
    int e = blockIdx.x * blockDim.x + threadIdx.x;
    if (e >= E) return;
    int d = g_dst[e];
    int pos = rowptr[d] + atomicAdd(&cur[d], 1);
    adj[pos] = g_src[e];
}

// ---------------- fp32 GEMM (f32x2 packed FMA) -> fp16, scaled by dinv -------
// feat[row, :] = half( dinv[row] * (A[row, :] @ [B0 | B1]) )
__global__ __launch_bounds__(256) void k_gemm(
    const float* __restrict__ A,
    const float* __restrict__ B0, const float* __restrict__ B1,
    int ldb0, int ldb1,
    const float* __restrict__ dinv,
    __half2* __restrict__ C, int N)
{
    __shared__ float As[8][64];
    __shared__ float Bs[8][128];

    int t  = threadIdx.x;
    int tx = t & 31;
    int ty = t >> 5;
    int row0 = blockIdx.x * 64;

    unsigned long long acc[8][2];
    #pragma unroll
    for (int i = 0; i < 8; i++) { acc[i][0] = 0ull; acc[i][1] = 0ull; }

    int lr = t >> 2;
    int lk = (t & 3) * 2;
    int bj = t & 127;
    int bkb = t >> 7;
    bool rowOK = (row0 + lr) < N;

    for (int k0 = 0; k0 < DIN; k0 += 8) {
        float a0 = 0.f, a1 = 0.f;
        if (rowOK) {
            const float* ap = &A[(size_t)(row0 + lr) * DIN + k0 + lk];
            a0 = ap[0]; a1 = ap[1];
        }
        As[lk][lr]     = a0;
        As[lk + 1][lr] = a1;

        #pragma unroll
        for (int u = 0; u < 4; u++) {
            int kk = bkb + u * 2;
            int kg = k0 + kk;
            float bv = (bj < 64) ? B0[kg * ldb0 + bj]
                                 : B1[kg * ldb1 + (bj - 64)];
            Bs[kk][bj] = bv;
        }
        __syncthreads();

        #pragma unroll
        for (int kk = 0; kk < 8; kk++) {
            float4 bv = *(const float4*)&Bs[kk][tx * 4];
            unsigned long long b01 = pk2(bv.x, bv.y);
            unsigned long long b23 = pk2(bv.z, bv.w);
            #pragma unroll
            for (int i = 0; i < 8; i++) {
                float av = As[kk][ty * 8 + i];
                unsigned long long ad = pk2(av, av);
                ffma2(acc[i][0], ad, b01);
                ffma2(acc[i][1], ad, b23);
            }
        }
        __syncthreads();
    }

    #pragma unroll
    for (int i = 0; i < 8; i++) {
        int grow = row0 + ty * 8 + i;
        if (grow < N) {
            float di = dinv[grow];
            float4 r;
            upk2(acc[i][0], r.x, r.y);
            upk2(acc[i][1], r.z, r.w);
            h2x2 o;
            o.a = __floats2half2_rn(r.x * di, r.y * di);
            o.b = __floats2half2_rn(r.z * di, r.w * di);
            *(h2x2*)&C[(size_t)grow * 64 + tx * 2] = o;
        }
    }
}

// fp16 row loader: 4 channels per lane (8 bytes)
__device__ __forceinline__ float4 ld_feat(const __half2* __restrict__ f,
                                          int row, int lane) {
    h2x2 v = *(const h2x2*)&f[(size_t)row * 64 + lane * 2];
    float2 fa = __half22float2(v.a);
    float2 fb = __half22float2(v.b);
    return make_float4(fa.x, fa.y, fb.x, fb.y);
}

// ---------------- gather layer 1: h = relu(dinv[d]*(self + sum) + b1) --------
__global__ __launch_bounds__(256) void k_gather1(
    const __half2* __restrict__ feat, const int* __restrict__ rowptr,
    const int* __restrict__ adj, const float* __restrict__ dinv,
    const float* __restrict__ b1, float* __restrict__ outh, int N)
{
    int node = (blockIdx.x * blockDim.x + threadIdx.x) >> 5;
    int lane = threadIdx.x & 31;
    if (node >= N) return;
    int beg = rowptr[node], end = rowptr[node + 1];

    float4 acc = ld_feat(feat, node, lane);   // self
    int p = beg;
    for (; p + 4 <= end; p += 4) {
        int s0 = __ldg(&adj[p]);
        int s1 = __ldg(&adj[p + 1]);
        int s2 = __ldg(&adj[p + 2]);
        int s3 = __ldg(&adj[p + 3]);
        float4 v0 = ld_feat(feat, s0, lane);
        float4 v1 = ld_feat(feat, s1, lane);
        float4 v2 = ld_feat(feat, s2, lane);
        float4 v3 = ld_feat(feat, s3, lane);
        acc.x += v0.x + v1.x + v2.x + v3.x;
        acc.y += v0.y + v1.y + v2.y + v3.y;
        acc.z += v0.z + v1.z + v2.z + v3.z;
        acc.w += v0.w + v1.w + v2.w + v3.w;
    }
    for (; p < end; p++) {
        int s = __ldg(&adj[p]);
        float4 v = ld_feat(feat, s, lane);
        acc.x += v.x; acc.y += v.y; acc.z += v.z; acc.w += v.w;
    }

    float di = dinv[node];
    float4 b = *(const float4*)&b1[lane * 4];
    float4 r;
    r.x = fmaxf(fmaf(di, acc.x, b.x), 0.f);
    r.y = fmaxf(fmaf(di, acc.y, b.y), 0.f);
    r.z = fmaxf(fmaf(di, acc.z, b.z), 0.f);
    r.w = fmaxf(fmaf(di, acc.w, b.w), 0.f);
    *(float4*)&outh[(size_t)node * DHID + lane * 4] = r;
}

// ---------------- gather layer 2: mu / logstd split --------------------------
__global__ __launch_bounds__(256) void k_gather2(
    const __half2* __restrict__ feat, const int* __restrict__ rowptr,
    const int* __restrict__ adj, const float* __restrict__ dinv,
    const float* __restrict__ bmu, const float* __restrict__ bls,
    float* __restrict__ out, int N)
{
    int node = (blockIdx.x * blockDim.x + threadIdx.x) >> 5;
    int lane = threadIdx.x & 31;
    if (node >= N) return;
    int beg = rowptr[node], end = rowptr[node + 1];

    float4 acc = ld_feat(feat, node, lane);   // self
    int p = beg;
    for (; p + 4 <= end; p += 4) {
        int s0 = __ldg(&adj[p]);
        int s1 = __ldg(&adj[p + 1]);
        int s2 = __ldg(&adj[p + 2]);
        int s3 = __ldg(&adj[p + 3]);
        float4 v0 = ld_feat(feat, s0, lane);
        float4 v1 = ld_feat(feat, s1, lane);
        float4 v2 = ld_feat(feat, s2, lane);
        float4 v3 = ld_feat(feat, s3, lane);
        acc.x += v0.x + v1.x + v2.x + v3.x;
        acc.y += v0.y + v1.y + v2.y + v3.y;
        acc.z += v0.z + v1.z + v2.z + v3.z;
        acc.w += v0.w + v1.w + v2.w + v3.w;
    }
    for (; p < end; p++) {
        int s = __ldg(&adj[p]);
        float4 v = ld_feat(feat, s, lane);
        acc.x += v.x; acc.y += v.y; acc.z += v.z; acc.w += v.w;
    }

    float di = dinv[node];
    int j = lane * 4;
    float4 r;
    if (j < DLAT) {
        float4 b = *(const float4*)&bmu[j];
        r.x = fmaf(di, acc.x, b.x);
        r.y = fmaf(di, acc.y, b.y);
        r.z = fmaf(di, acc.z, b.z);
        r.w = fmaf(di, acc.w, b.w);
        *(float4*)&out[(size_t)node * DLAT + j] = r;
    } else {
        float4 b = *(const float4*)&bls[j - DLAT];
        r.x = fmaf(di, acc.x, b.x);
        r.y = fmaf(di, acc.y, b.y);
        r.z = fmaf(di, acc.z, b.z);
        r.w = fmaf(di, acc.w, b.w);
        *(float4*)&out[(size_t)N * DLAT + (size_t)node * DLAT + (j - DLAT)] = r;
    }
}

// ---------------- launch ------------------------------------------------------
extern "C" void kernel_launch(void* const* d_in, const int* in_sizes, int n_in,
                              void* d_out, int out_size)
{
    const float* x   = (const float*)d_in[0];
    const void*  ei  = d_in[1];
    const float* W1  = (const float*)d_in[2];
    const float* b1  = (const float*)d_in[3];
    const float* Wmu = (const float*)d_in[4];
    const float* bmu = (const float*)d_in[5];
    const float* Wls = (const float*)d_in[6];
    const float* bls = (const float*)d_in[7];
    float*       out = (float*)d_out;

    int N = in_sizes[0] / DIN;     // 100000
    int E = in_sizes[1] / 2;       // 1600000
    (void)n_in; (void)out_size;

    __half2* feat;
    float *bufH, *dinv;
    int *cnt, *rowptr, *part, *adj;
    cudaGetSymbolAddress((void**)&feat, g_feat);
    cudaGetSymbolAddress((void**)&bufH, g_bufH);
    cudaGetSymbolAddress((void**)&dinv, g_dinv);
    cudaGetSymbolAddress((void**)&cnt, g_cnt);
    cudaGetSymbolAddress((void**)&rowptr, g_rowptr);
    cudaGetSymbolAddress((void**)&part, g_part);
    cudaGetSymbolAddress((void**)&adj, g_adj);

    int B = (N + 255) / 256;       // scan blocks (391)

    // ---- edge preprocessing: detect, convert+histogram, scan, fill ----
    k_detect<<<1, 32>>>((const long long*)ei, N);
    cudaMemsetAsync(cnt, 0, (size_t)N * sizeof(int), 0);
    k_convert<<<(E + 255) / 256, 256>>>(ei, E, cnt);
    k_scan1<<<B, 256>>>(cnt, rowptr, part, N);
    k_scan2<<<1, 512>>>(part, B);
    k_scan3<<<B, 256>>>(rowptr, part, cnt, dinv, N, E);
    k_fill<<<(E + 255) / 256, 256>>>(E, rowptr, cnt, adj);

    // ---- layer 1 ----
    k_gemm<<<(N + 63) / 64, 256>>>(x, W1, W1 + 64, DHID, DHID, dinv, feat, N);
    k_gather1<<<(N * 32 + 255) / 256, 256>>>(feat, rowptr, adj, dinv, b1, bufH, N);

    // ---- layer 2 (mu | logstd fused) ----
    k_gemm<<<(N + 63) / 64, 256>>>(bufH, Wmu, Wls, DLAT, DLAT, dinv, feat, N);
    k_gather2<<<(N * 32 + 255) / 256, 256>>>(feat, rowptr, adj, dinv, bmu, bls, out, N);
}

// round 5
// speedup vs baseline: 3.6975x; 1.6550x over previous
#include <cuda_runtime.h>
#include <cuda_fp16.h>
#include <cstdint>

#define NMAX 100000
#define EMAX 1600000
#define DIN  128
#define DHID 128
#define DLAT 64

// ---------------- scratch ----------------------------------------------------
struct alignas(8) h2x2 { __half2 a, b; };

__device__ __half2 g_feat[(size_t)NMAX * 64];   // fp16 feat' (dinv-scaled GEMM out)
__device__ __half2 g_bufH[(size_t)NMAX * 64];   // hidden h (fp16)
__device__ __half  g_W1h[DIN * DHID];           // fp16 W1
__device__ __half  g_W2h[DHID * DHID];          // fp16 [Wmu | Wls]
__device__ float   g_dinv[NMAX];
__device__ int     g_adj[EMAX];                 // CSR: src per slot
__device__ int     g_rowptr[NMAX + 1];
__device__ int     g_cnt[NMAX];                 // histogram, then cursor
__device__ int     g_part[512];
__device__ int     g_idx64;

// ---------------- mma helpers --------------------------------------------------
__device__ __forceinline__ uint32_t cvs(const void* p) {
    return (uint32_t)__cvta_generic_to_shared(p);
}

__device__ __forceinline__ void ldsm4(uint32_t* r, uint32_t addr) {
    asm volatile("ldmatrix.sync.aligned.m8n8.x4.shared.b16 {%0,%1,%2,%3}, [%4];"
                 : "=r"(r[0]), "=r"(r[1]), "=r"(r[2]), "=r"(r[3]) : "r"(addr));
}
__device__ __forceinline__ void ldsm4t(uint32_t* r, uint32_t addr) {
    asm volatile("ldmatrix.sync.aligned.m8n8.x4.trans.shared.b16 {%0,%1,%2,%3}, [%4];"
                 : "=r"(r[0]), "=r"(r[1]), "=r"(r[2]), "=r"(r[3]) : "r"(addr));
}
__device__ __forceinline__ void mma16816(float* c, const uint32_t* a,
                                         uint32_t b0, uint32_t b1) {
    asm volatile(
        "mma.sync.aligned.m16n8k16.row.col.f32.f16.f16.f32 "
        "{%0,%1,%2,%3},{%4,%5,%6,%7},{%8,%9},{%0,%1,%2,%3};"
        : "+f"(c[0]), "+f"(c[1]), "+f"(c[2]), "+f"(c[3])
        : "r"(a[0]), "r"(a[1]), "r"(a[2]), "r"(a[3]), "r"(b0), "r"(b1));
}

// ---------------- edge dtype detection ---------------------------------------
__global__ void k_detect(const long long* ei, int N) {
    if (threadIdx.x == 0 && blockIdx.x == 0) {
        int ok64 = 1;
        #pragma unroll
        for (int k = 0; k < 8; k++) {
            long long v = ei[k];
            if (v < 0 || v >= (long long)N) ok64 = 0;
        }
        g_idx64 = ok64;
    }
}

// ---------------- histogram over dst (reads edge_index directly) -------------
__global__ void k_hist(const void* ei, int E, int* cnt) {
    int e = blockIdx.x * blockDim.x + threadIdx.x;
    if (e >= E) return;
    int d = g_idx64 ? (int)((const long long*)ei)[(size_t)E + e]
                    : ((const int*)ei)[E + e];
    atomicAdd(&cnt[d], 1);
}

// ---------------- two-level exclusive scan over cnt -> rowptr ----------------
__global__ void k_scan1(const int* cnt, int* rowptr, int* part, int N) {
    __shared__ int sh[256];
    int i = blockIdx.x * 256 + threadIdx.x;
    int v = (i < N) ? cnt[i] : 0;
    sh[threadIdx.x] = v;
    __syncthreads();
    for (int off = 1; off < 256; off <<= 1) {
        int t = (threadIdx.x >= (unsigned)off) ? sh[threadIdx.x - off] : 0;
        __syncthreads();
        sh[threadIdx.x] += t;
        __syncthreads();
    }
    if (i < N) rowptr[i] = sh[threadIdx.x] - v;      // exclusive
    if (threadIdx.x == 255) part[blockIdx.x] = sh[255];
}

__global__ void k_scan2(int* part, int B) {
    __shared__ int sh[512];
    int v = (threadIdx.x < (unsigned)B) ? part[threadIdx.x] : 0;
    sh[threadIdx.x] = v;
    __syncthreads();
    for (int off = 1; off < 512; off <<= 1) {
        int t = (threadIdx.x >= (unsigned)off) ? sh[threadIdx.x - off] : 0;
        __syncthreads();
        sh[threadIdx.x] += t;
        __syncthreads();
    }
    if (threadIdx.x < (unsigned)B) part[threadIdx.x] = sh[threadIdx.x] - v;  // exclusive
}

__global__ void k_scan3(int* rowptr, const int* part, int* cnt, float* dinv,
                        int N, int E) {
    int i = blockIdx.x * 256 + threadIdx.x;
    if (i < N) {
        rowptr[i] += part[blockIdx.x];
        dinv[i] = rsqrtf((float)(cnt[i] + 1));   // +1 self-loop
        cnt[i] = 0;                               // reset as fill cursor
    }
    if (i == 0) rowptr[N] = E;
}

__global__ void k_fill(const void* ei, int E, const int* rowptr, int* cur, int* adj) {
    int e = blockIdx.x * blockDim.x + threadIdx.x;
    if (e >= E) return;
    int s, d;
    if (g_idx64) {
        const long long* p = (const long long*)ei;
        s = (int)p[e];
        d = (int)p[(size_t)E + e];
    } else {
        const int* p = (const int*)ei;
        s = p[e];
        d = p[E + e];
    }
    int pos = rowptr[d] + atomicAdd(&cur[d], 1);
    adj[pos] = s;
}

// ---------------- weight conversion to fp16 ----------------------------------
__global__ void k_wconv(const float* W1, const float* Wmu, const float* Wls,
                        __half* W1h, __half* W2h) {
    int i = blockIdx.x * 256 + threadIdx.x;
    if (i >= DIN * DHID) return;
    W1h[i] = __float2half_rn(W1[i]);
    int k = i >> 7, n = i & 127;
    float v = (n < 64) ? Wmu[k * 64 + n] : Wls[k * 64 + (n - 64)];
    W2h[i] = __float2half_rn(v);
}

// ---------------- tensor-core GEMM: feat = fp16(dinv * (A @ Bh)) --------------
// Block: 128 rows x 128 cols, 256 threads (8 warps, warp tile 32x64).
// K processed in two 64-chunks. A is fp32 (AF16=0) or fp16 (AF16=1).
template<int AF16>
__global__ __launch_bounds__(256) void k_gemm_mma(
    const void* __restrict__ Ain, const __half* __restrict__ Bh,
    const float* __restrict__ dinv, __half2* __restrict__ C, int N)
{
    __shared__ __half As[128][72];    // 144B row stride: conflict-free ldmatrix
    __shared__ __half Bs[64][136];    // 272B row stride: conflict-free ldmatrix

    int t = threadIdx.x, lane = t & 31, wid = t >> 5;
    int warp_m = wid & 3, warp_n = wid >> 2;
    int rowBase = blockIdx.x * 128;

    float acc[2][8][4];
    #pragma unroll
    for (int mt = 0; mt < 2; mt++)
        #pragma unroll
        for (int nt = 0; nt < 8; nt++)
            #pragma unroll
            for (int q = 0; q < 4; q++) acc[mt][nt][q] = 0.f;

    #pragma unroll
    for (int kc = 0; kc < 2; kc++) {
        // ---- load A chunk (128 rows x 64 k-cols) ----
        if (AF16) {
            const __half* A = (const __half*)Ain;
            #pragma unroll
            for (int i = 0; i < 8; i++) {
                int g = t + i * 256;             // 0..2047
                int r = g >> 4, c4 = (g & 15) * 4;
                int grow = rowBase + r;
                uint2 v = make_uint2(0u, 0u);
                if (grow < N) v = *(const uint2*)&A[(size_t)grow * DHID + kc * 64 + c4];
                *(uint2*)&As[r][c4] = v;
            }
        } else {
            const float* A = (const float*)Ain;
            #pragma unroll
            for (int i = 0; i < 8; i++) {
                int g = t + i * 256;
                int r = g >> 4, c4 = (g & 15) * 4;
                int grow = rowBase + r;
                float4 v = make_float4(0.f, 0.f, 0.f, 0.f);
                if (grow < N) v = *(const float4*)&A[(size_t)grow * DIN + kc * 64 + c4];
                *(__half2*)&As[r][c4]     = __floats2half2_rn(v.x, v.y);
                *(__half2*)&As[r][c4 + 2] = __floats2half2_rn(v.z, v.w);
            }
        }
        // ---- load B chunk (64 k-rows x 128 cols, fp16 source) ----
        #pragma unroll
        for (int i = 0; i < 4; i++) {
            int g = t + i * 256;                 // 0..1023
            int r = g >> 4, c8 = (g & 15) * 8;
            uint4 v = *(const uint4*)&Bh[(size_t)(kc * 64 + r) * DHID + c8];
            *(uint4*)&Bs[r][c8] = v;
        }
        __syncthreads();

        #pragma unroll
        for (int ks = 0; ks < 4; ks++) {
            uint32_t a[2][4];
            #pragma unroll
            for (int mt = 0; mt < 2; mt++) {
                uint32_t ad = cvs(&As[warp_m * 32 + mt * 16 + (lane & 15)]
                                     [ks * 16 + (lane >> 4) * 8]);
                ldsm4(a[mt], ad);
            }
            uint32_t b[4][4];
            #pragma unroll
            for (int n2 = 0; n2 < 4; n2++) {
                uint32_t ad = cvs(&Bs[ks * 16 + (lane & 15)]
                                     [warp_n * 64 + n2 * 16 + (lane >> 4) * 8]);
                ldsm4t(b[n2], ad);
            }
            #pragma unroll
            for (int mt = 0; mt < 2; mt++)
                #pragma unroll
                for (int nt = 0; nt < 8; nt++)
                    mma16816(acc[mt][nt], a[mt],
                             b[nt >> 1][(nt & 1) * 2], b[nt >> 1][(nt & 1) * 2 + 1]);
        }
        __syncthreads();
    }

    // ---- epilogue: scale by dinv, fp16 store ----
    #pragma unroll
    for (int mt = 0; mt < 2; mt++) {
        int r0 = rowBase + warp_m * 32 + mt * 16 + (lane >> 2);
        int r1 = r0 + 8;
        float d0 = (r0 < N) ? dinv[r0] : 0.f;
        float d1 = (r1 < N) ? dinv[r1] : 0.f;
        #pragma unroll
        for (int nt = 0; nt < 8; nt++) {
            int ch = (warp_n * 64 + nt * 8 + (lane & 3) * 2) >> 1;
            if (r0 < N)
                C[(size_t)r0 * 64 + ch] =
                    __floats2half2_rn(acc[mt][nt][0] * d0, acc[mt][nt][1] * d0);
            if (r1 < N)
                C[(size_t)r1 * 64 + ch] =
                    __floats2half2_rn(acc[mt][nt][2] * d1, acc[mt][nt][3] * d1);
        }
    }
}

// fp16 row loader: 4 channels per lane (8 bytes)
__device__ __forceinline__ float4 ld_feat(const __half2* __restrict__ f,
                                          int row, int lane) {
    h2x2 v = *(const h2x2*)&f[(size_t)row * 64 + lane * 2];
    float2 fa = __half22float2(v.a);
    float2 fb = __half22float2(v.b);
    return make_float4(fa.x, fa.y, fb.x, fb.y);
}

// ---------------- gather layer 1: h = relu(dinv[d]*(self + sum) + b1) --------
__global__ __launch_bounds__(256) void k_gather1(
    const __half2* __restrict__ feat, const int* __restrict__ rowptr,
    const int* __restrict__ adj, const float* __restrict__ dinv,
    const float* __restrict__ b1, __half2* __restrict__ outh, int N)
{
    int node = (blockIdx.x * blockDim.x + threadIdx.x) >> 5;
    int lane = threadIdx.x & 31;
    if (node >= N) return;
    int beg = rowptr[node], end = rowptr[node + 1];

    float4 acc = ld_feat(feat, node, lane);   // self
    int p = beg;
    for (; p + 4 <= end; p += 4) {
        int s0 = __ldg(&adj[p]);
        int s1 = __ldg(&adj[p + 1]);
        int s2 = __ldg(&adj[p + 2]);
        int s3 = __ldg(&adj[p + 3]);
        float4 v0 = ld_feat(feat, s0, lane);
        float4 v1 = ld_feat(feat, s1, lane);
        float4 v2 = ld_feat(feat, s2, lane);
        float4 v3 = ld_feat(feat, s3, lane);
        acc.x += v0.x + v1.x + v2.x + v3.x;
        acc.y += v0.y + v1.y + v2.y + v3.y;
        acc.z += v0.z + v1.z + v2.z + v3.z;
        acc.w += v0.w + v1.w + v2.w + v3.w;
    }
    for (; p < end; p++) {
        int s = __ldg(&adj[p]);
        float4 v = ld_feat(feat, s, lane);
        acc.x += v.x; acc.y += v.y; acc.z += v.z; acc.w += v.w;
    }

    float di = dinv[node];
    float4 b = *(const float4*)&b1[lane * 4];
    h2x2 o;
    o.a = __floats2half2_rn(fmaxf(fmaf(di, acc.x, b.x), 0.f),
                            fmaxf(fmaf(di, acc.y, b.y), 0.f));
    o.b = __floats2half2_rn(fmaxf(fmaf(di, acc.z, b.z), 0.f),
                            fmaxf(fmaf(di, acc.w, b.w), 0.f));
    *(h2x2*)&outh[(size_t)node * 64 + lane * 2] = o;
}

// ---------------- gather layer 2: mu / logstd split --------------------------
__global__ __launch_bounds__(256) void k_gather2(
    const __half2* __restrict__ feat, const int* __restrict__ rowptr,
    const int* __restrict__ adj, const float* __restrict__ dinv,
    const float* __restrict__ bmu, const float* __restrict__ bls,
    float* __restrict__ out, int N)
{
    int node = (blockIdx.x * blockDim.x + threadIdx.x) >> 5;
    int lane = threadIdx.x & 31;
    if (node >= N) return;
    int beg = rowptr[node], end = rowptr[node + 1];

    float4 acc = ld_feat(feat, node, lane);   // self
    int p = beg;
    for (; p + 4 <= end; p += 4) {
        int s0 = __ldg(&adj[p]);
        int s1 = __ldg(&adj[p + 1]);
        int s2 = __ldg(&adj[p + 2]);
        int s3 = __ldg(&adj[p + 3]);
        float4 v0 = ld_feat(feat, s0, lane);
        float4 v1 = ld_feat(feat, s1, lane);
        float4 v2 = ld_feat(feat, s2, lane);
        float4 v3 = ld_feat(feat, s3, lane);
        acc.x += v0.x + v1.x + v2.x + v3.x;
        acc.y += v0.y + v1.y + v2.y + v3.y;
        acc.z += v0.z + v1.z + v2.z + v3.z;
        acc.w += v0.w + v1.w + v2.w + v3.w;
    }
    for (; p < end; p++) {
        int s = __ldg(&adj[p]);
        float4 v = ld_feat(feat, s, lane);
        acc.x += v.x; acc.y += v.y; acc.z += v.z; acc.w += v.w;
    }

    float di = dinv[node];
    int j = lane * 4;
    float4 r;
    if (j < DLAT) {
        float4 b = *(const float4*)&bmu[j];
        r.x = fmaf(di, acc.x, b.x);
        r.y = fmaf(di, acc.y, b.y);
        r.z = fmaf(di, acc.z, b.z);
        r.w = fmaf(di, acc.w, b.w);
        *(float4*)&out[(size_t)node * DLAT + j] = r;
    } else {
        float4 b = *(const float4*)&bls[j - DLAT];
        r.x = fmaf(di, acc.x, b.x);
        r.y = fmaf(di, acc.y, b.y);
        r.z = fmaf(di, acc.z, b.z);
        r.w = fmaf(di, acc.w, b.w);
        *(float4*)&out[(size_t)N * DLAT + (size_t)node * DLAT + (j - DLAT)] = r;
    }
}

// ---------------- launch ------------------------------------------------------
extern "C" void kernel_launch(void* const* d_in, const int* in_sizes, int n_in,
                              void* d_out, int out_size)
{
    const float* x   = (const float*)d_in[0];
    const void*  ei  = d_in[1];
    const float* W1  = (const float*)d_in[2];
    const float* b1  = (const float*)d_in[3];
    const float* Wmu = (const float*)d_in[4];
    const float* bmu = (const float*)d_in[5];
    const float* Wls = (const float*)d_in[6];
    const float* bls = (const float*)d_in[7];
    float*       out = (float*)d_out;

    int N = in_sizes[0] / DIN;     // 100000
    int E = in_sizes[1] / 2;       // 1600000
    (void)n_in; (void)out_size;

    __half2 *feat, *bufH;
    __half *W1h, *W2h;
    float* dinv;
    int *cnt, *rowptr, *part, *adj;
    cudaGetSymbolAddress((void**)&feat, g_feat);
    cudaGetSymbolAddress((void**)&bufH, g_bufH);
    cudaGetSymbolAddress((void**)&W1h, g_W1h);
    cudaGetSymbolAddress((void**)&W2h, g_W2h);
    cudaGetSymbolAddress((void**)&dinv, g_dinv);
    cudaGetSymbolAddress((void**)&cnt, g_cnt);
    cudaGetSymbolAddress((void**)&rowptr, g_rowptr);
    cudaGetSymbolAddress((void**)&part, g_part);
    cudaGetSymbolAddress((void**)&adj, g_adj);

    int B = (N + 255) / 256;       // scan blocks (391)

    // ---- edge preprocessing + weight conversion ----
    k_detect<<<1, 32>>>((const long long*)ei, N);
    k_wconv<<<(DIN * DHID + 255) / 256, 256>>>(W1, Wmu, Wls, W1h, W2h);
    cudaMemsetAsync(cnt, 0, (size_t)N * sizeof(int), 0);
    k_hist<<<(E + 255) / 256, 256>>>(ei, E, cnt);
    k_scan1<<<B, 256>>>(cnt, rowptr, part, N);
    k_scan2<<<1, 512>>>(part, B);
    k_scan3<<<B, 256>>>(rowptr, part, cnt, dinv, N, E);
    k_fill<<<(E + 255) / 256, 256>>>(ei, E, rowptr, cnt, adj);

    int gemmBlocks = (N + 127) / 128;

    // ---- layer 1 ----
    k_gemm_mma<0><<<gemmBlocks, 256>>>(x, W1h, dinv, feat, N);
    k_gather1<<<(N * 32 + 255) / 256, 256>>>(feat, rowptr, adj, dinv, b1, bufH, N);

    // ---- layer 2 (mu | logstd fused) ----
    k_gemm_mma<1><<<gemmBlocks, 256>>>(bufH, W2h, dinv, feat, N);
    k_gather2<<<(N * 32 + 255) / 256, 256>>>(feat, rowptr, adj, dinv, bmu, bls, out, N);
}